// round 2
// baseline (speedup 1.0000x reference)
#include <cuda_runtime.h>

#define NGROUPS 8
#define THREADS 256
#define ITER 8                       // elements per thread per tile
#define TILE (THREADS * ITER)        // 2048 rows per block-tile
#define MAX_BLOCKS 4096

// Scratch (no allocations allowed). g_part is fully overwritten each run;
// g_counter is reset to 0 by the last block each run (deterministic).
__device__ float    g_part[MAX_BLOCKS * 2 * NGROUPS];
__device__ unsigned g_counter = 0;

__device__ __forceinline__ void block_reduce_16(float* s, float* c,
                                                float* red /* [THREADS/32][16] */) {
    // warp reduce
#pragma unroll
    for (int j = 0; j < NGROUPS; j++) {
#pragma unroll
        for (int o = 16; o > 0; o >>= 1) {
            s[j] += __shfl_down_sync(0xffffffffu, s[j], o);
            c[j] += __shfl_down_sync(0xffffffffu, c[j], o);
        }
    }
    int lane = threadIdx.x & 31;
    int warp = threadIdx.x >> 5;
    if (lane == 0) {
#pragma unroll
        for (int j = 0; j < NGROUPS; j++) {
            red[warp * 16 + j]          = s[j];
            red[warp * 16 + NGROUPS + j] = c[j];
        }
    }
    __syncthreads();
    if (threadIdx.x < 2 * NGROUPS) {
        float t = 0.0f;
#pragma unroll
        for (int w = 0; w < THREADS / 32; w++) t += red[w * 16 + threadIdx.x];
        red[threadIdx.x] = t;   // result in red[0..15]
    }
    __syncthreads();
}

__global__ __launch_bounds__(THREADS) void fused_kernel(
    const float* __restrict__ in, const int* __restrict__ tgt,
    const int* __restrict__ grp, float* __restrict__ out, int n)
{
    __shared__ float red[(THREADS / 32) * 16];
    __shared__ bool  is_last;

    float s[NGROUPS], c[NGROUPS];
#pragma unroll
    for (int j = 0; j < NGROUPS; j++) { s[j] = 0.0f; c[j] = 0.0f; }

    int ntiles = (n + TILE - 1) / TILE;

    for (int tile = blockIdx.x; tile < ntiles; tile += gridDim.x) {
        int base = tile * TILE + threadIdx.x;

        // Phase A: batch all index loads (independent, coalesced: lanes
        // consecutive). 16 LDGs in flight per thread.
        int t[ITER], g[ITER];
#pragma unroll
        for (int k = 0; k < ITER; k++) {
            int i = base + k * THREADS;
            bool ok = (i < n);
            t[k] = ok ? __ldcs(tgt + i) : 0;
            g[k] = ok ? __ldcs(grp + i) : -1;
        }

        // Phase B: batch all gathers (independent; 2 rows share a 128B line
        // since lanes map to consecutive rows). 8 more LDGs in flight.
        float v[ITER];
#pragma unroll
        for (int k = 0; k < ITER; k++) {
            int i = base + k * THREADS;
            v[k] = (i < n) ? __ldcs(in + ((size_t)i << 4) + t[k]) : 0.0f;
        }

        // Phase C: accumulate
#pragma unroll
        for (int k = 0; k < ITER; k++) {
            float e = fabsf(1.0f - v[k]);
#pragma unroll
            for (int j = 0; j < NGROUPS; j++) {
                bool m = (g[k] == j);
                s[j] += m ? e : 0.0f;
                c[j] += m ? 1.0f : 0.0f;    // exact in f32 (< 2^24)
            }
        }
    }

    block_reduce_16(s, c, red);

    // write per-block partials
    if (threadIdx.x < 2 * NGROUPS)
        g_part[blockIdx.x * 2 * NGROUPS + threadIdx.x] = red[threadIdx.x];
    __syncthreads();

    // last-block-done
    if (threadIdx.x == 0) {
        __threadfence();
        unsigned v = atomicAdd(&g_counter, 1u);
        is_last = (v == gridDim.x - 1);
    }
    __syncthreads();
    if (!is_last) return;

    // Final reduction over all block partials
    float fs[NGROUPS], fc[NGROUPS];
#pragma unroll
    for (int j = 0; j < NGROUPS; j++) { fs[j] = 0.0f; fc[j] = 0.0f; }
    for (int b = threadIdx.x; b < gridDim.x; b += THREADS) {
#pragma unroll
        for (int j = 0; j < NGROUPS; j++) {
            fs[j] += g_part[b * 2 * NGROUPS + j];
            fc[j] += g_part[b * 2 * NGROUPS + NGROUPS + j];
        }
    }
    __syncthreads();
    block_reduce_16(fs, fc, red);

    if (threadIdx.x == 0) {
        float msum = 0.0f;
#pragma unroll
        for (int j = 0; j < NGROUPS; j++) {
            float cnt = red[NGROUPS + j];
            msum += (cnt > 0.0f) ? (red[j] / cnt) : 0.0f;
        }
        out[0] = fabsf(0.5f - msum * (1.0f / NGROUPS));
        g_counter = 0;   // reset for next graph replay (deterministic)
    }
}

extern "C" void kernel_launch(void* const* d_in, const int* in_sizes, int n_in,
                              void* d_out, int out_size) {
    const float* in  = (const float*)d_in[0];
    const int*   tgt = (const int*)d_in[1];
    const int*   grp = (const int*)d_in[2];
    float*       out = (float*)d_out;
    int n = in_sizes[1];  // N rows

    int blocks = (n + TILE - 1) / TILE;          // 2048 for N = 4M
    if (blocks > MAX_BLOCKS) blocks = MAX_BLOCKS;
    if (blocks < 1) blocks = 1;
    fused_kernel<<<blocks, THREADS>>>(in, tgt, grp, out, n);
}